// round 6
// baseline (speedup 1.0000x reference)
#include <cuda_runtime.h>
#include <cstdint>

// ---------------------------------------------------------------------------
// Problem: x[B,2] f32, ws[10] f32, B = 16777216.
//   step: nx0 = x0 - 0.1*x1
//         nx1 = (1 + 0.1*w)*x1 + 0.1*x0 - 0.1*x0^3
//   out  = (tanh(100(x1-0.1)) - tanh(100(x1+0.1)) + 2)/2
//
// Rescaled state: x0 = 10*p,  x1 = -100*nq  (track negated q)
//   p'  = p + nq
//   nq' = A*nq + nw,  nw = p*(p^2 - 0.01),  A = 1 + 0.1*w
// 4-op step (packed f32x2), rt-weighted cost 9/step/chain on the banked
// fp32 pipe:
//   in  = fma(P, P, -0.01)   // 2 distinct 64b srcs -> rt2
//   nw  = in * P             // rt2
//   p'  = P + NQ             // rt2
//   nq' = fma(A, NQ, nw)     // 3 distinct srcs -> rt3
// Epilogue: 100*x1 -+ 10 = -10000*nq -+ 10 -> FFMA-imm (rt1) + MUFU.TANH.
// ---------------------------------------------------------------------------

#define FMA2(d, a, b, c) \
    asm("fma.rn.f32x2 %0, %1, %2, %3;" : "=l"(d) : "l"(a), "l"(b), "l"(c))
#define MUL2(d, a, b) \
    asm("mul.rn.f32x2 %0, %1, %2;" : "=l"(d) : "l"(a), "l"(b))
#define ADD2(d, a, b) \
    asm("add.rn.f32x2 %0, %1, %2;" : "=l"(d) : "l"(a), "l"(b))

__device__ unsigned long long g_a_packed[10];  // splat(1 + 0.1*ws[k])

__global__ void prep_kernel(const float* __restrict__ ws) {
    int i = threadIdx.x;
    if (i < 10) {
        float a = fmaf(0.1f, ws[i], 1.0f);
        unsigned int u = __float_as_uint(a);
        g_a_packed[i] = ((unsigned long long)u << 32) | (unsigned long long)u;
    }
}

__device__ __forceinline__ float tanh_approx(float x) {
    float r; asm("tanh.approx.f32 %0, %1;" : "=f"(r) : "f"(x)); return r;
}

// out = 0.5*tanh(-10000*nq - 10) - 0.5*tanh(-10000*nq + 10) + 1
__device__ __forceinline__ float notch_nq(float nq) {
    float t1 = tanh_approx(fmaf(-10000.0f, nq, -10.0f));
    float t2 = tanh_approx(fmaf(-10000.0f, nq,  10.0f));
    return fmaf(0.5f, t1, fmaf(-0.5f, t2, 1.0f));
}

// 4 points per thread: two independent packed-f32x2 recurrence chains.
__global__ __launch_bounds__(256) void nn_kernel(
    const float4* __restrict__ x, float4* __restrict__ out, int n4)
{
    int i = blockIdx.x * blockDim.x + threadIdx.x;
    if (i >= n4) return;

    float4 va = x[2 * i];      // points 0,1
    float4 vb = x[2 * i + 1];  // points 2,3

    unsigned long long X0a, X1a, X0b, X1b;
    asm("mov.b64 %0, {%1, %2};" : "=l"(X0a) : "f"(va.x), "f"(va.z));
    asm("mov.b64 %0, {%1, %2};" : "=l"(X1a) : "f"(va.y), "f"(va.w));
    asm("mov.b64 %0, {%1, %2};" : "=l"(X0b) : "f"(vb.x), "f"(vb.z));
    asm("mov.b64 %0, {%1, %2};" : "=l"(X1b) : "f"(vb.y), "f"(vb.w));

    const unsigned long long C01   = 0x3DCCCCCD3DCCCCCDULL;  // splat(+0.1f)
    const unsigned long long NC001 = 0xBC23D70ABC23D70AULL;  // splat(-0.01f)

    // Scale into (p, nq): p = 0.1*x0, nq = -0.01*x1
    unsigned long long Pa, NQa, Pb, NQb;
    MUL2(Pa,  X0a, C01);
    MUL2(NQa, X1a, NC001);
    MUL2(Pb,  X0b, C01);
    MUL2(NQb, X1b, NC001);

    #pragma unroll
    for (int k = 0; k < 10; k++) {
        unsigned long long A = g_a_packed[k];  // uniform (L1 broadcast)

        unsigned long long ina, nwa, pa2, nqa2;
        unsigned long long inb, nwb, pb2, nqb2;
        // Two independent chains interleaved for dual-issue latency hiding.
        FMA2(ina,  Pa, Pa, NC001);    // p^2 - 0.01   (2 distinct srcs, rt2)
        FMA2(inb,  Pb, Pb, NC001);
        MUL2(nwa,  ina, Pa);          // p^3 - 0.01p = -w
        MUL2(nwb,  inb, Pb);
        ADD2(pa2,  Pa, NQa);          // p' = p - q
        ADD2(pb2,  Pb, NQb);
        FMA2(nqa2, A, NQa, nwa);      // nq' = A*nq - w
        FMA2(nqb2, A, NQb, nwb);
        Pa = pa2;  NQa = nqa2;
        Pb = pb2;  NQb = nqb2;
    }

    float nq0, nq1, nq2, nq3;
    asm("mov.b64 {%0, %1}, %2;" : "=f"(nq0), "=f"(nq1) : "l"(NQa));
    asm("mov.b64 {%0, %1}, %2;" : "=f"(nq2), "=f"(nq3) : "l"(NQb));

    float4 o;
    o.x = notch_nq(nq0);
    o.y = notch_nq(nq1);
    o.z = notch_nq(nq2);
    o.w = notch_nq(nq3);
    out[i] = o;  // 16B coalesced store of 4 outputs
}

extern "C" void kernel_launch(void* const* d_in, const int* in_sizes, int n_in,
                              void* d_out, int out_size) {
    // Robust input identification: ws is the 10-element tensor.
    const float* x;
    const float* ws;
    if (n_in >= 2 && in_sizes[0] == 10) {
        ws = (const float*)d_in[0];
        x  = (const float*)d_in[1];
    } else {
        x  = (const float*)d_in[0];
        ws = (const float*)d_in[1];
    }

    prep_kernel<<<1, 32>>>(ws);

    int n4 = out_size / 4;  // 4 points per thread (B = 2^24, divisible)
    int blocks = (n4 + 255) / 256;
    nn_kernel<<<blocks, 256>>>((const float4*)x, (float4*)d_out, n4);
}

// round 8
// speedup vs baseline: 1.0785x; 1.0785x over previous
#include <cuda_runtime.h>
#include <cstdint>

// ---------------------------------------------------------------------------
// Problem: x[B,2] f32, ws[10] f32, B = 16777216.
//   step: nx0 = x0 - 0.1*x1
//         nx1 = (1 + 0.1*w)*x1 + 0.1*x0 - 0.1*x0^3
//   out  = (tanh(100(x1-0.1)) - tanh(100(x1+0.1)) + 2)/2
//
// Rescaled state: x0 = 10*p,  x1 = -100*nq  (track negated q)
//   p'  = p + nq
//   nq' = A*nq + nw,  nw = p*(p^2 - 0.01),  A = 1 + 0.1*w
// 4-op step (packed f32x2), rt-weighted cost 9/step/chain on the banked
// fp32 pipe:
//   in  = fma(P, P, -0.01)   // 2 distinct 64b srcs -> rt2
//   nw  = in * P             // rt2
//   p'  = P + NQ             // rt2
//   nq' = fma(A, NQ, nw)     // 3 distinct srcs -> rt3
// Epilogue: 100*x1 -+ 10 = -10000*nq -+ 10 -> FFMA-imm (rt1) + MUFU.TANH.
//
// Single-kernel design: the 10 splat-packed coefficients A[k] are computed
// per block into shared memory (threads 0..9 + one barrier) instead of a
// separate prep kernel — removes the second graph node and its launch/
// serialization overhead from every replay.
// ---------------------------------------------------------------------------

#define FMA2(d, a, b, c) \
    asm("fma.rn.f32x2 %0, %1, %2, %3;" : "=l"(d) : "l"(a), "l"(b), "l"(c))
#define MUL2(d, a, b) \
    asm("mul.rn.f32x2 %0, %1, %2;" : "=l"(d) : "l"(a), "l"(b))
#define ADD2(d, a, b) \
    asm("add.rn.f32x2 %0, %1, %2;" : "=l"(d) : "l"(a), "l"(b))

__device__ __forceinline__ float tanh_approx(float x) {
    float r; asm("tanh.approx.f32 %0, %1;" : "=f"(r) : "f"(x)); return r;
}

// out = 0.5*tanh(-10000*nq - 10) - 0.5*tanh(-10000*nq + 10) + 1
__device__ __forceinline__ float notch_nq(float nq) {
    float t1 = tanh_approx(fmaf(-10000.0f, nq, -10.0f));
    float t2 = tanh_approx(fmaf(-10000.0f, nq,  10.0f));
    return fmaf(0.5f, t1, fmaf(-0.5f, t2, 1.0f));
}

// 4 points per thread: two independent packed-f32x2 recurrence chains.
__global__ __launch_bounds__(256) void nn_kernel(
    const float4* __restrict__ x, const float* __restrict__ ws,
    float4* __restrict__ out, int n4)
{
    __shared__ unsigned long long sA[10];

    // Per-block coefficient prep: A[k] = splat(1 + 0.1*ws[k]).
    if (threadIdx.x < 10) {
        float a = fmaf(0.1f, __ldg(ws + threadIdx.x), 1.0f);
        unsigned int u = __float_as_uint(a);
        sA[threadIdx.x] = ((unsigned long long)u << 32) | (unsigned long long)u;
    }

    int i = blockIdx.x * blockDim.x + threadIdx.x;

    // Issue the data loads before the barrier so DRAM latency overlaps it.
    float4 va, vb;
    if (i < n4) {
        va = x[2 * i];      // points 0,1
        vb = x[2 * i + 1];  // points 2,3
    }

    __syncthreads();

    if (i >= n4) return;

    unsigned long long X0a, X1a, X0b, X1b;
    asm("mov.b64 %0, {%1, %2};" : "=l"(X0a) : "f"(va.x), "f"(va.z));
    asm("mov.b64 %0, {%1, %2};" : "=l"(X1a) : "f"(va.y), "f"(va.w));
    asm("mov.b64 %0, {%1, %2};" : "=l"(X0b) : "f"(vb.x), "f"(vb.z));
    asm("mov.b64 %0, {%1, %2};" : "=l"(X1b) : "f"(vb.y), "f"(vb.w));

    const unsigned long long C01   = 0x3DCCCCCD3DCCCCCDULL;  // splat(+0.1f)
    const unsigned long long NC001 = 0xBC23D70ABC23D70AULL;  // splat(-0.01f)

    // Scale into (p, nq): p = 0.1*x0, nq = -0.01*x1
    unsigned long long Pa, NQa, Pb, NQb;
    MUL2(Pa,  X0a, C01);
    MUL2(NQa, X1a, NC001);
    MUL2(Pb,  X0b, C01);
    MUL2(NQb, X1b, NC001);

    #pragma unroll
    for (int k = 0; k < 10; k++) {
        unsigned long long A = sA[k];  // immediate-offset LDS, broadcast

        unsigned long long ina, nwa, pa2, nqa2;
        unsigned long long inb, nwb, pb2, nqb2;
        // Two independent chains interleaved for dual-issue latency hiding.
        FMA2(ina,  Pa, Pa, NC001);    // p^2 - 0.01   (2 distinct srcs, rt2)
        FMA2(inb,  Pb, Pb, NC001);
        MUL2(nwa,  ina, Pa);          // p^3 - 0.01p = -w
        MUL2(nwb,  inb, Pb);
        ADD2(pa2,  Pa, NQa);          // p' = p - q
        ADD2(pb2,  Pb, NQb);
        FMA2(nqa2, A, NQa, nwa);      // nq' = A*nq - w
        FMA2(nqb2, A, NQb, nwb);
        Pa = pa2;  NQa = nqa2;
        Pb = pb2;  NQb = nqb2;
    }

    float nq0, nq1, nq2, nq3;
    asm("mov.b64 {%0, %1}, %2;" : "=f"(nq0), "=f"(nq1) : "l"(NQa));
    asm("mov.b64 {%0, %1}, %2;" : "=f"(nq2), "=f"(nq3) : "l"(NQb));

    float4 o;
    o.x = notch_nq(nq0);
    o.y = notch_nq(nq1);
    o.z = notch_nq(nq2);
    o.w = notch_nq(nq3);
    out[i] = o;  // 16B coalesced store of 4 outputs
}

extern "C" void kernel_launch(void* const* d_in, const int* in_sizes, int n_in,
                              void* d_out, int out_size) {
    // Robust input identification: ws is the 10-element tensor.
    const float* x;
    const float* ws;
    if (n_in >= 2 && in_sizes[0] == 10) {
        ws = (const float*)d_in[0];
        x  = (const float*)d_in[1];
    } else {
        x  = (const float*)d_in[0];
        ws = (const float*)d_in[1];
    }

    int n4 = out_size / 4;  // 4 points per thread (B = 2^24, divisible)
    int blocks = (n4 + 255) / 256;
    nn_kernel<<<blocks, 256>>>((const float4*)x, ws, (float4*)d_out, n4);
}

// round 12
// speedup vs baseline: 1.1242x; 1.0423x over previous
#include <cuda_runtime.h>
#include <cstdint>

// ---------------------------------------------------------------------------
// Problem: x[B,2] f32, ws[10] f32, B = 16777216.
//   step: nx0 = x0 - 0.1*x1
//         nx1 = (1 + 0.1*w)*x1 + 0.1*x0 - 0.1*x0^3
//   out  = (tanh(100(x1-0.1)) - tanh(100(x1+0.1)) + 2)/2
//
// Rescaled state: x0 = 10*p,  x1 = -100*nq  (track negated q)
//   p'  = p + nq
//   nq' = A*nq + nw,  nw = p*(p^2 - 0.01),  A = 1 + 0.1*w
// 4-op step (packed f32x2), rt-weighted cost 9/step/chain on the banked
// fp32 pipe:
//   in  = fma(P, P, -0.01)   // 2 distinct 64b srcs -> rt2
//   nw  = in * P             // rt2
//   p'  = P + NQ             // rt2
//   nq' = fma(A, NQ, nw)     // 3 distinct srcs -> rt3
// Epilogue: 100*x1 -+ 10 = -10000*nq -+ 10 -> FFMA-imm (rt1) + MUFU.TANH.
//
// R9: 8 points/thread = 4 independent packed chains. Front-batched 4x
// LDG.128 (MLP_p1=4) for deeper DRAM queues; halves warp count so LDS
// coefficient reads, index ALU and barrier cost amortize over 2x points.
// Coefficients A[k] computed per block into smem (no prep kernel).
// ---------------------------------------------------------------------------

#define FMA2(d, a, b, c) \
    asm("fma.rn.f32x2 %0, %1, %2, %3;" : "=l"(d) : "l"(a), "l"(b), "l"(c))
#define MUL2(d, a, b) \
    asm("mul.rn.f32x2 %0, %1, %2;" : "=l"(d) : "l"(a), "l"(b))
#define ADD2(d, a, b) \
    asm("add.rn.f32x2 %0, %1, %2;" : "=l"(d) : "l"(a), "l"(b))

__device__ __forceinline__ float tanh_approx(float x) {
    float r; asm("tanh.approx.f32 %0, %1;" : "=f"(r) : "f"(x)); return r;
}

// out = 0.5*tanh(-10000*nq - 10) - 0.5*tanh(-10000*nq + 10) + 1
// (both combine FMAs are immediate-multiplier form -> rt1)
__device__ __forceinline__ float notch_nq(float nq) {
    float t1 = tanh_approx(fmaf(-10000.0f, nq, -10.0f));
    float t2 = tanh_approx(fmaf(-10000.0f, nq,  10.0f));
    return fmaf(0.5f, t1, fmaf(-0.5f, t2, 1.0f));
}

__global__ __launch_bounds__(256) void nn_kernel(
    const float4* __restrict__ x, const float* __restrict__ ws,
    float4* __restrict__ out, int n8)
{
    __shared__ unsigned long long sA[10];

    // Per-block coefficient prep: A[k] = splat(1 + 0.1*ws[k]).
    if (threadIdx.x < 10) {
        float a = fmaf(0.1f, __ldg(ws + threadIdx.x), 1.0f);
        unsigned int u = __float_as_uint(a);
        sA[threadIdx.x] = ((unsigned long long)u << 32) | (unsigned long long)u;
    }

    int i = blockIdx.x * blockDim.x + threadIdx.x;

    // Front-batched loads (MLP_p1 = 4): 64B contiguous per thread,
    // 2KB contiguous per warp. Latency overlaps the barrier below.
    float4 va, vb, vc, vd;
    if (i < n8) {
        const float4* xp = x + 4 * (long)i;
        va = xp[0];  // points 0,1
        vb = xp[1];  // points 2,3
        vc = xp[2];  // points 4,5
        vd = xp[3];  // points 6,7
    }

    __syncthreads();

    if (i >= n8) return;

    unsigned long long X0a, X1a, X0b, X1b, X0c, X1c, X0d, X1d;
    asm("mov.b64 %0, {%1, %2};" : "=l"(X0a) : "f"(va.x), "f"(va.z));
    asm("mov.b64 %0, {%1, %2};" : "=l"(X1a) : "f"(va.y), "f"(va.w));
    asm("mov.b64 %0, {%1, %2};" : "=l"(X0b) : "f"(vb.x), "f"(vb.z));
    asm("mov.b64 %0, {%1, %2};" : "=l"(X1b) : "f"(vb.y), "f"(vb.w));
    asm("mov.b64 %0, {%1, %2};" : "=l"(X0c) : "f"(vc.x), "f"(vc.z));
    asm("mov.b64 %0, {%1, %2};" : "=l"(X1c) : "f"(vc.y), "f"(vc.w));
    asm("mov.b64 %0, {%1, %2};" : "=l"(X0d) : "f"(vd.x), "f"(vd.z));
    asm("mov.b64 %0, {%1, %2};" : "=l"(X1d) : "f"(vd.y), "f"(vd.w));

    const unsigned long long C01   = 0x3DCCCCCD3DCCCCCDULL;  // splat(+0.1f)
    const unsigned long long NC001 = 0xBC23D70ABC23D70AULL;  // splat(-0.01f)

    // Scale into (p, nq): p = 0.1*x0, nq = -0.01*x1
    unsigned long long Pa, NQa, Pb, NQb, Pc, NQc, Pd, NQd;
    MUL2(Pa,  X0a, C01);   MUL2(NQa, X1a, NC001);
    MUL2(Pb,  X0b, C01);   MUL2(NQb, X1b, NC001);
    MUL2(Pc,  X0c, C01);   MUL2(NQc, X1c, NC001);
    MUL2(Pd,  X0d, C01);   MUL2(NQd, X1d, NC001);

    #pragma unroll
    for (int k = 0; k < 10; k++) {
        unsigned long long A = sA[k];  // immediate-offset LDS, broadcast

        unsigned long long ina, nwa, pa2, nqa2;
        unsigned long long inb, nwb, pb2, nqb2;
        unsigned long long inc, nwc, pc2, nqc2;
        unsigned long long ind, nwd, pd2, nqd2;
        // Four independent chains interleaved for ILP.
        FMA2(ina,  Pa, Pa, NC001);    // p^2 - 0.01
        FMA2(inb,  Pb, Pb, NC001);
        FMA2(inc,  Pc, Pc, NC001);
        FMA2(ind,  Pd, Pd, NC001);
        MUL2(nwa,  ina, Pa);          // p^3 - 0.01p = -w
        MUL2(nwb,  inb, Pb);
        MUL2(nwc,  inc, Pc);
        MUL2(nwd,  ind, Pd);
        ADD2(pa2,  Pa, NQa);          // p' = p - q
        ADD2(pb2,  Pb, NQb);
        ADD2(pc2,  Pc, NQc);
        ADD2(pd2,  Pd, NQd);
        FMA2(nqa2, A, NQa, nwa);      // nq' = A*nq - w
        FMA2(nqb2, A, NQb, nwb);
        FMA2(nqc2, A, NQc, nwc);
        FMA2(nqd2, A, NQd, nwd);
        Pa = pa2;  NQa = nqa2;
        Pb = pb2;  NQb = nqb2;
        Pc = pc2;  NQc = nqc2;
        Pd = pd2;  NQd = nqd2;
    }

    float q0, q1, q2, q3, q4, q5, q6, q7;
    asm("mov.b64 {%0, %1}, %2;" : "=f"(q0), "=f"(q1) : "l"(NQa));
    asm("mov.b64 {%0, %1}, %2;" : "=f"(q2), "=f"(q3) : "l"(NQb));
    asm("mov.b64 {%0, %1}, %2;" : "=f"(q4), "=f"(q5) : "l"(NQc));
    asm("mov.b64 {%0, %1}, %2;" : "=f"(q6), "=f"(q7) : "l"(NQd));

    float4 o0, o1;
    o0.x = notch_nq(q0);  o0.y = notch_nq(q1);
    o0.z = notch_nq(q2);  o0.w = notch_nq(q3);
    o1.x = notch_nq(q4);  o1.y = notch_nq(q5);
    o1.z = notch_nq(q6);  o1.w = notch_nq(q7);

    float4* op = out + 2 * (long)i;
    op[0] = o0;   // 2x 16B coalesced stores of 8 outputs
    op[1] = o1;
}

extern "C" void kernel_launch(void* const* d_in, const int* in_sizes, int n_in,
                              void* d_out, int out_size) {
    // Robust input identification: ws is the 10-element tensor.
    const float* x;
    const float* ws;
    if (n_in >= 2 && in_sizes[0] == 10) {
        ws = (const float*)d_in[0];
        x  = (const float*)d_in[1];
    } else {
        x  = (const float*)d_in[0];
        ws = (const float*)d_in[1];
    }

    int n8 = out_size / 8;  // 8 points per thread (B = 2^24, divisible)
    int blocks = (n8 + 255) / 256;
    nn_kernel<<<blocks, 256>>>((const float4*)x, ws, (float4*)d_out, n8);
}

// round 13
// speedup vs baseline: 1.1979x; 1.0656x over previous
#include <cuda_runtime.h>
#include <cstdint>

// ---------------------------------------------------------------------------
// Problem: x[B,2] f32, ws[10] f32, B = 16777216.
//   step: nx0 = x0 - 0.1*x1
//         nx1 = (1 + 0.1*w)*x1 + 0.1*x0 - 0.1*x0^3
//   out  = (tanh(100(x1-0.1)) - tanh(100(x1+0.1)) + 2)/2
//
// Rescaled state: x0 = 10*p,  x1 = -100*nq  (track negated q)
//   p'  = p + nq
//   nq' = A*nq + nw,  nw = p*(p^2 - 0.01),  A = 1 + 0.1*w
// 4-op packed-f32x2 step, rt-weighted cost 9/step/chain on the banked pipe.
// Epilogue: 100*x1 -+ 10 = -10000*nq -+ 10 -> FFMA-imm (rt1) + MUFU.TANH.
//
// R13: kernel is at the HBM floor (201 MB one-touch stream, ~6.8 TB/s
// achieved). Add evict-first streaming hints (ld/st.global.cs) on the bulk
// stream — data has zero reuse and exceeds the 126 MB L2, so evict-normal
// policy only thrashes. 8 points/thread = 4 independent chains (MLP_p1=4);
// coefficients A[k] built per block in smem (single-kernel graph).
// ---------------------------------------------------------------------------

#define FMA2(d, a, b, c) \
    asm("fma.rn.f32x2 %0, %1, %2, %3;" : "=l"(d) : "l"(a), "l"(b), "l"(c))
#define MUL2(d, a, b) \
    asm("mul.rn.f32x2 %0, %1, %2;" : "=l"(d) : "l"(a), "l"(b))
#define ADD2(d, a, b) \
    asm("add.rn.f32x2 %0, %1, %2;" : "=l"(d) : "l"(a), "l"(b))

// Streaming (evict-first) 128-bit load/store.
__device__ __forceinline__ float4 ldcs4(const float4* p) {
    float4 v;
    asm("ld.global.cs.v4.f32 {%0, %1, %2, %3}, [%4];"
        : "=f"(v.x), "=f"(v.y), "=f"(v.z), "=f"(v.w) : "l"(p));
    return v;
}
__device__ __forceinline__ void stcs4(float4* p, float4 v) {
    asm("st.global.cs.v4.f32 [%0], {%1, %2, %3, %4};"
        :: "l"(p), "f"(v.x), "f"(v.y), "f"(v.z), "f"(v.w) : "memory");
}

__device__ __forceinline__ float tanh_approx(float x) {
    float r; asm("tanh.approx.f32 %0, %1;" : "=f"(r) : "f"(x)); return r;
}

// out = 0.5*(tanh(-10000*nq - 10) - tanh(-10000*nq + 10)) + 1
__device__ __forceinline__ float notch_nq(float nq) {
    float t1 = tanh_approx(fmaf(-10000.0f, nq, -10.0f));
    float t2 = tanh_approx(fmaf(-10000.0f, nq,  10.0f));
    return fmaf(0.5f, t1 - t2, 1.0f);
}

__global__ __launch_bounds__(256) void nn_kernel(
    const float4* __restrict__ x, const float* __restrict__ ws,
    float4* __restrict__ out, int n8)
{
    __shared__ unsigned long long sA[10];

    // Per-block coefficient prep: A[k] = splat(1 + 0.1*ws[k]).
    if (threadIdx.x < 10) {
        float a = fmaf(0.1f, __ldg(ws + threadIdx.x), 1.0f);
        unsigned int u = __float_as_uint(a);
        sA[threadIdx.x] = ((unsigned long long)u << 32) | (unsigned long long)u;
    }

    int i = blockIdx.x * blockDim.x + threadIdx.x;

    // Front-batched streaming loads (MLP_p1 = 4): 64B contiguous per thread,
    // 2KB contiguous per warp. Latency overlaps the barrier below.
    float4 va, vb, vc, vd;
    if (i < n8) {
        const float4* xp = x + 4 * (long)i;
        va = ldcs4(xp + 0);  // points 0,1
        vb = ldcs4(xp + 1);  // points 2,3
        vc = ldcs4(xp + 2);  // points 4,5
        vd = ldcs4(xp + 3);  // points 6,7
    }

    __syncthreads();

    if (i >= n8) return;

    unsigned long long X0a, X1a, X0b, X1b, X0c, X1c, X0d, X1d;
    asm("mov.b64 %0, {%1, %2};" : "=l"(X0a) : "f"(va.x), "f"(va.z));
    asm("mov.b64 %0, {%1, %2};" : "=l"(X1a) : "f"(va.y), "f"(va.w));
    asm("mov.b64 %0, {%1, %2};" : "=l"(X0b) : "f"(vb.x), "f"(vb.z));
    asm("mov.b64 %0, {%1, %2};" : "=l"(X1b) : "f"(vb.y), "f"(vb.w));
    asm("mov.b64 %0, {%1, %2};" : "=l"(X0c) : "f"(vc.x), "f"(vc.z));
    asm("mov.b64 %0, {%1, %2};" : "=l"(X1c) : "f"(vc.y), "f"(vc.w));
    asm("mov.b64 %0, {%1, %2};" : "=l"(X0d) : "f"(vd.x), "f"(vd.z));
    asm("mov.b64 %0, {%1, %2};" : "=l"(X1d) : "f"(vd.y), "f"(vd.w));

    const unsigned long long C01   = 0x3DCCCCCD3DCCCCCDULL;  // splat(+0.1f)
    const unsigned long long NC001 = 0xBC23D70ABC23D70AULL;  // splat(-0.01f)

    // Scale into (p, nq): p = 0.1*x0, nq = -0.01*x1
    unsigned long long Pa, NQa, Pb, NQb, Pc, NQc, Pd, NQd;
    MUL2(Pa,  X0a, C01);   MUL2(NQa, X1a, NC001);
    MUL2(Pb,  X0b, C01);   MUL2(NQb, X1b, NC001);
    MUL2(Pc,  X0c, C01);   MUL2(NQc, X1c, NC001);
    MUL2(Pd,  X0d, C01);   MUL2(NQd, X1d, NC001);

    #pragma unroll
    for (int k = 0; k < 10; k++) {
        unsigned long long A = sA[k];  // immediate-offset LDS, broadcast

        unsigned long long ina, nwa, pa2, nqa2;
        unsigned long long inb, nwb, pb2, nqb2;
        unsigned long long inc, nwc, pc2, nqc2;
        unsigned long long ind, nwd, pd2, nqd2;
        // Four independent chains interleaved for ILP.
        FMA2(ina,  Pa, Pa, NC001);    // p^2 - 0.01
        FMA2(inb,  Pb, Pb, NC001);
        FMA2(inc,  Pc, Pc, NC001);
        FMA2(ind,  Pd, Pd, NC001);
        MUL2(nwa,  ina, Pa);          // p^3 - 0.01p = -w
        MUL2(nwb,  inb, Pb);
        MUL2(nwc,  inc, Pc);
        MUL2(nwd,  ind, Pd);
        ADD2(pa2,  Pa, NQa);          // p' = p - q
        ADD2(pb2,  Pb, NQb);
        ADD2(pc2,  Pc, NQc);
        ADD2(pd2,  Pd, NQd);
        FMA2(nqa2, A, NQa, nwa);      // nq' = A*nq - w
        FMA2(nqb2, A, NQb, nwb);
        FMA2(nqc2, A, NQc, nwc);
        FMA2(nqd2, A, NQd, nwd);
        Pa = pa2;  NQa = nqa2;
        Pb = pb2;  NQb = nqb2;
        Pc = pc2;  NQc = nqc2;
        Pd = pd2;  NQd = nqd2;
    }

    float q0, q1, q2, q3, q4, q5, q6, q7;
    asm("mov.b64 {%0, %1}, %2;" : "=f"(q0), "=f"(q1) : "l"(NQa));
    asm("mov.b64 {%0, %1}, %2;" : "=f"(q2), "=f"(q3) : "l"(NQb));
    asm("mov.b64 {%0, %1}, %2;" : "=f"(q4), "=f"(q5) : "l"(NQc));
    asm("mov.b64 {%0, %1}, %2;" : "=f"(q6), "=f"(q7) : "l"(NQd));

    float4 o0, o1;
    o0.x = notch_nq(q0);  o0.y = notch_nq(q1);
    o0.z = notch_nq(q2);  o0.w = notch_nq(q3);
    o1.x = notch_nq(q4);  o1.y = notch_nq(q5);
    o1.z = notch_nq(q6);  o1.w = notch_nq(q7);

    float4* op = out + 2 * (long)i;
    stcs4(op + 0, o0);   // 2x 16B streaming stores of 8 outputs
    stcs4(op + 1, o1);
}

extern "C" void kernel_launch(void* const* d_in, const int* in_sizes, int n_in,
                              void* d_out, int out_size) {
    // Robust input identification: ws is the 10-element tensor.
    const float* x;
    const float* ws;
    if (n_in >= 2 && in_sizes[0] == 10) {
        ws = (const float*)d_in[0];
        x  = (const float*)d_in[1];
    } else {
        x  = (const float*)d_in[0];
        ws = (const float*)d_in[1];
    }

    int n8 = out_size / 8;  // 8 points per thread (B = 2^24, divisible)
    int blocks = (n8 + 255) / 256;
    nn_kernel<<<blocks, 256>>>((const float4*)x, ws, (float4*)d_out, n8);
}